// round 14
// baseline (speedup 1.0000x reference)
#include <cuda_runtime.h>
#include <cuda_fp16.h>
#include <cstdint>
#include <cstddef>

#define TT   20
#define BB   64
#define NNF  196
#define VOC  10000
#define G4   2048
#define NBLK 64           // persistent LSTM grid (8 u-dims per block)

// ---------------- static device scratch ----------------
__device__ float g_fmean[BB * 512];
__device__ float g_ctx  [BB * 512];
__device__ float g_attl [BB * NNF];
__device__ float g_gpre [TT * BB * G4];
__device__ float g_words[TT * BB * VOC];
__device__ unsigned long long g_bar;   // monotonic across replays

__device__ __half g_Wout16[VOC * 512];
__device__ __half g_Wih16 [G4 * 1024];
__device__ __half g_A16   [TT * BB * 1024];
__device__ __half g_hall  [TT * BB * 512];
__device__ __half g_hb16  [2][BB * 512];

// ---------------- helpers ----------------
__device__ __forceinline__ uint32_t smem_u32(const void* p) {
    uint32_t a;
    asm("{ .reg .u64 t; cvta.to.shared.u64 t, %1; cvt.u32.u64 %0, t; }"
        : "=r"(a) : "l"(p));
    return a;
}
__device__ __forceinline__ void ldm_x4(uint32_t* r, uint32_t addr) {
    asm volatile("ldmatrix.sync.aligned.m8n8.x4.shared.b16 {%0,%1,%2,%3}, [%4];"
                 : "=r"(r[0]), "=r"(r[1]), "=r"(r[2]), "=r"(r[3]) : "r"(addr));
}
__device__ __forceinline__ void mma_fp16(float* d, const uint32_t* a, const uint32_t* b) {
    asm volatile(
        "mma.sync.aligned.m16n8k16.row.col.f32.f16.f16.f32 "
        "{%0,%1,%2,%3}, {%4,%5,%6,%7}, {%8,%9}, {%0,%1,%2,%3};"
        : "+f"(d[0]), "+f"(d[1]), "+f"(d[2]), "+f"(d[3])
        : "r"(a[0]), "r"(a[1]), "r"(a[2]), "r"(a[3]), "r"(b[0]), "r"(b[1]));
}
__device__ __forceinline__ void cpa16(uint32_t dst, const void* src, int srcsz) {
    asm volatile("cp.async.cg.shared.global [%0], [%1], 16, %2;"
                 :: "r"(dst), "l"(src), "r"(srcsz));
}
__device__ __forceinline__ void cpa_commit() {
    asm volatile("cp.async.commit_group;");
}
template<int NG> __device__ __forceinline__ void cpa_wait() {
    asm volatile("cp.async.wait_group %0;" :: "n"(NG));
}

// ============ single-pass fp16 GEMM: C[m,n] = sum_k A[m,k]*B[n,k] ==========
// BM=128, BN=128, BK=32; 8 warps (4x2); warp tile 32x64.
#define ASTR 40                         // padded fp16 row stride (80B)
#define BUFB (128 * ASTR * 2)           // one operand buffer: 10240 bytes
#define STAGEB (2 * BUFB)               // A|B per stage: 20480 bytes

__global__ void __launch_bounds__(256) gemm_mma(
    const __half* __restrict__ A, const __half* __restrict__ B,
    float* __restrict__ C, int N, int ldc, int K,
    const float* __restrict__ bias0, const float* __restrict__ bias1)
{
    extern __shared__ __align__(16) __half dsm[];
    const uint32_t smb = smem_u32(dsm);

    const int tid  = threadIdx.x;
    const int lane = tid & 31;
    const int w    = tid >> 5;
    const int wm   = w >> 1;
    const int wn   = w & 1;
    const int m0   = blockIdx.x * 128;
    const int n0   = blockIdx.y * 128;
    const int mbase = wm * 32;
    const int nbase = wn * 64;
    const int g = lane >> 2;
    const int q = lane & 3;

    const int i0 = tid, i1 = tid + 256;
    const int r0s = i0 >> 2, k0s = (i0 & 3) * 8;
    const int r1s = i1 >> 2, k1s = (i1 & 3) * 8;
    const int bsz0 = (n0 + r0s) < N ? 16 : 0;
    const int bsz1 = (n0 + r1s) < N ? 16 : 0;
    const uint32_t d0 = (uint32_t)(r0s * ASTR + k0s) * 2;
    const uint32_t d1 = (uint32_t)(r1s * ASTR + k1s) * 2;

    const int l7 = lane & 7;
    const uint32_t aRow = mbase + l7 + ((lane >> 3) & 1) * 8;
    const uint32_t aKof = (lane >> 4) * 16;
    const uint32_t bRow = nbase + l7 + (lane >> 4) * 8;
    const uint32_t bKof = ((lane >> 3) & 1) * 16;

    float acc[2][8][4];
    #pragma unroll
    for (int mt = 0; mt < 2; mt++)
        #pragma unroll
        for (int nt = 0; nt < 8; nt++)
            #pragma unroll
            for (int r = 0; r < 4; r++) acc[mt][nt][r] = 0.f;

    const int nk = K / 32;

    auto load_stage = [&](int kt, int s) {
        const int k0 = kt * 32;
        const uint32_t sb = smb + (uint32_t)s * STAGEB;
        cpa16(sb + d0,        A + (size_t)(m0 + r0s) * K + k0 + k0s, 16);
        cpa16(sb + d1,        A + (size_t)(m0 + r1s) * K + k0 + k1s, 16);
        cpa16(sb + BUFB + d0, B + (size_t)(n0 + r0s) * K + k0 + k0s, bsz0);
        cpa16(sb + BUFB + d1, B + (size_t)(n0 + r1s) * K + k0 + k1s, bsz1);
        cpa_commit();
    };

    load_stage(0, 0);

    for (int kt = 0; kt < nk; kt++) {
        if (kt + 1 < nk) load_stage(kt + 1, (kt + 1) & 1);
        if (kt + 1 < nk) cpa_wait<1>(); else cpa_wait<0>();
        __syncthreads();

        const uint32_t sb = smb + (uint32_t)(kt & 1) * STAGEB;
        const uint32_t bA = sb, bB = sb + BUFB;

        #pragma unroll
        for (int kk = 0; kk < 2; kk++) {
            const uint32_t kb = kk * 32;
            uint32_t ah[2][4];
            #pragma unroll
            for (int mt = 0; mt < 2; mt++) {
                const uint32_t ro = (aRow + mt * 16) * (ASTR * 2) + kb + aKof;
                ldm_x4(ah[mt], bA + ro);
            }
            #pragma unroll
            for (int np = 0; np < 4; np++) {
                const uint32_t ro = (bRow + np * 16) * (ASTR * 2) + kb + bKof;
                uint32_t tb[4];
                ldm_x4(tb, bB + ro);
                uint32_t bh0[2] = {tb[0], tb[1]}, bh1[2] = {tb[2], tb[3]};
                #pragma unroll
                for (int mt = 0; mt < 2; mt++) {
                    mma_fp16(acc[mt][np * 2 + 0], ah[mt], bh0);
                    mma_fp16(acc[mt][np * 2 + 1], ah[mt], bh1);
                }
            }
        }
        __syncthreads();
    }

    #pragma unroll
    for (int mt = 0; mt < 2; mt++) {
        #pragma unroll
        for (int nt = 0; nt < 8; nt++) {
            const int n = n0 + nbase + nt * 8 + q * 2;
            if (n < N) {
                #pragma unroll
                for (int half = 0; half < 2; half++) {
                    const int m = m0 + mbase + mt * 16 + g + half * 8;
                    float v0 = acc[mt][nt][half * 2 + 0];
                    float v1 = acc[mt][nt][half * 2 + 1];
                    if (bias0) { v0 += bias0[n]; v1 += bias0[n + 1]; }
                    if (bias1) { v0 += bias1[n]; v1 += bias1[n + 1]; }
                    *(float2*)(C + (size_t)m * ldc + n) = make_float2(v0, v1);
                }
            }
        }
    }
}

// ---------------- fp32 -> fp16, 8 elems/thread ----------------
__global__ void __launch_bounds__(256) cvt_hi8(
    const float* __restrict__ src, __half* __restrict__ hi, int total)
{
    const int i = (blockIdx.x * 256 + threadIdx.x) * 8;
    if (i < total) {
        float4 x0 = *(const float4*)(src + i);
        float4 x1 = *(const float4*)(src + i + 4);
        float xs[8] = {x0.x, x0.y, x0.z, x0.w, x1.x, x1.y, x1.z, x1.w};
        __half h8[8];
        #pragma unroll
        for (int j = 0; j < 8; j++) h8[j] = __float2half_rn(xs[j]);
        *(uint4*)(hi + i) = *(const uint4*)h8;
    }
}

// ---------------- concat A = [ctx(b) | embed(tok)] fp16 (rowmap inline) ------
__global__ void __launch_bounds__(256) cvt_concat8(const float* __restrict__ embed,
                                                   const int* __restrict__ captions) {
    const int i = (blockIdx.x * 256 + threadIdx.x) * 8;
    if (i < TT * BB * 1024) {
        const int r = i >> 10, k = i & 1023;
        const int b = r & 63, t = r >> 6;
        const float* sp;
        if (k < 512) {
            sp = g_ctx + b * 512 + k;
        } else {
            const int tok = captions[b * TT + t];
            sp = embed + (size_t)tok * 512 + (k - 512);
        }
        float4 x0 = *(const float4*)sp;
        float4 x1 = *(const float4*)(sp + 4);
        float xs[8] = {x0.x, x0.y, x0.z, x0.w, x1.x, x1.y, x1.z, x1.w};
        __half h8[8];
        #pragma unroll
        for (int j = 0; j < 8; j++) h8[j] = __float2half_rn(xs[j]);
        *(uint4*)(g_A16 + i) = *(const uint4*)h8;
    }
}

// ---------------- attention logits (parallel, 896 blocks) ----------------
__global__ void __launch_bounds__(256) attn_dot(const float* __restrict__ features,
                                                const float* __restrict__ W_av) {
    const int b   = blockIdx.x;
    const int n0  = blockIdx.y * 14;
    __shared__ float sW[512];
    const int tid = threadIdx.x;
    const int wid = tid >> 5, lane = tid & 31;
    for (int i = tid; i < 512; i += 256) sW[i] = W_av[i];
    __syncthreads();

    const float* fb = features + (size_t)b * NNF * 512;
    for (int n = n0 + wid; n < n0 + 14 && n < NNF; n += 8) {
        const float* fr = fb + (size_t)n * 512;
        float s0 = 0.f, s1 = 0.f, s2 = 0.f, s3 = 0.f;
        #pragma unroll
        for (int i = 0; i < 4; i++) {
            const int o = lane + i * 128;
            s0 = fmaf(fr[o],      sW[o],      s0);
            s1 = fmaf(fr[o + 32], sW[o + 32], s1);
            s2 = fmaf(fr[o + 64], sW[o + 64], s2);
            s3 = fmaf(fr[o + 96], sW[o + 96], s3);
        }
        float s = (s0 + s1) + (s2 + s3);
        #pragma unroll
        for (int o = 16; o; o >>= 1) s += __shfl_down_sync(0xffffffffu, s, o);
        if (!lane) g_attl[b * NNF + n] = s;
    }
}

// ------- ctx + fmean with fused softmax weights: grid (BB, 8), 512 thr -------
__global__ void __launch_bounds__(512) attn_ctx(const float* __restrict__ features) {
    const int b  = blockIdx.x;
    const int v0 = blockIdx.y * 64;
    const int tid = threadIdx.x;
    const int c  = tid & 63;
    const int rg = tid >> 6;          // 0..7, rows rg*25..+24
    __shared__ float sw[NNF];
    __shared__ float sred[16];
    __shared__ float sM, sI;
    __shared__ float pac[8][64];
    __shared__ float pam[8][64];
    const int wid = tid >> 5, lane = tid & 31;

    float m = -3.0e38f;
    if (tid < NNF) { m = g_attl[b * NNF + tid]; sw[tid] = m; }
    #pragma unroll
    for (int o = 16; o; o >>= 1) m = fmaxf(m, __shfl_down_sync(0xffffffffu, m, o));
    if (!lane) sred[wid] = m;
    __syncthreads();
    if (tid == 0) {
        float mm = sred[0];
        #pragma unroll
        for (int i = 1; i < 16; i++) mm = fmaxf(mm, sred[i]);
        sM = mm;
    }
    __syncthreads();
    float e = 0.f;
    if (tid < NNF) { e = __expf(sw[tid] - sM); sw[tid] = e; }
    float s = e;
    #pragma unroll
    for (int o = 16; o; o >>= 1) s += __shfl_down_sync(0xffffffffu, s, o);
    if (!lane) sred[wid] = s;
    __syncthreads();
    if (tid == 0) {
        float ss = 0.f;
        #pragma unroll
        for (int i = 0; i < 16; i++) ss += sred[i];
        sI = 1.f / ss;
    }
    __syncthreads();
    const float inv = sI;

    const float* fp = features + (size_t)b * NNF * 512 + v0 + c;
    float ac = 0.f, am = 0.f;
    const int nb = rg * 25;
    #pragma unroll 5
    for (int j = 0; j < 25; j++) {
        const int n = nb + j;
        if (n < NNF) {
            const float f = fp[(size_t)n * 512];
            ac = fmaf(sw[n], f, ac);
            am += f;
        }
    }
    pac[rg][c] = ac;
    pam[rg][c] = am;
    __syncthreads();
    if (rg == 0) {
        float a = 0.f, mm = 0.f;
        #pragma unroll
        for (int i = 0; i < 8; i++) { a += pac[i][c]; mm += pam[i][c]; }
        g_ctx  [b * 512 + v0 + c] = a * inv;
        g_fmean[b * 512 + v0 + c] = mm * (1.f / (float)NNF);
    }
}

// ====== persistent HMMA LSTM: 64 blocks x 8 u-dims, shuffle-free cell =========
__device__ __forceinline__ void gbar() {
    __syncthreads();
    if (threadIdx.x == 0) {
        unsigned long long old;
        asm volatile("atom.release.gpu.global.add.u64 %0, [%1], %2;"
                     : "=l"(old) : "l"(&g_bar), "l"(1ULL) : "memory");
        unsigned long long tgt = old - (old & (unsigned long long)(NBLK - 1)) + (unsigned long long)NBLK;
        unsigned long long cur;
        do {
            asm volatile("ld.global.acquire.gpu.u64 %0, [%1];" : "=l"(cur) : "l"(&g_bar));
        } while (cur < tgt);
    }
    __syncthreads();
}

#define STRH 520   // fp16 row stride for sW/sH (1040 B, conflict-free ldmatrix)

// sW: 32 rows = [i u0..u0+7 | f ... | g ... | o ...];  sH: 64 batches.
// D fragment: lane (r=lane>>2, q=lane&3) holds, for batches b0i=w*8+q*2 (+1):
//   mt=0: i(u=r) b0,b1 ; f(u=r) b0,b1     mt=1: g(u=r) b0,b1 ; o(u=r) b0,b1
__global__ void __launch_bounds__(256, 1) lstm_kernel(
    const float* __restrict__ Winit_h, const float* __restrict__ Winit_c,
    const float* __restrict__ Whh)
{
    extern __shared__ __half smh[];
    __half* sW = smh;                 // [32][STRH]
    __half* sH = smh + 32 * STRH;     // [64][STRH]

    const int tid  = threadIdx.x;
    const int w    = tid >> 5;
    const int lane = tid & 31;
    const int l7   = lane & 7;
    const int r    = lane >> 2;       // 0..7  (u offset)
    const int q    = lane & 3;
    const int u0   = blockIdx.x * 8;

    const uint32_t sWb = smem_u32(sW);
    const uint32_t sHb = smem_u32(sH);
    const uint32_t aOff = (uint32_t)((l7 + ((lane >> 3) & 1) * 8) * (STRH * 2) + (lane >> 4) * 16);
    const uint32_t bOff = (uint32_t)((w * 8 + l7) * (STRH * 2) + (lane >> 3) * 16);

    // ---- phase 0: sW rows 0-7 = Winit_h[u0+j], 8-15 = Winit_c[u0+j], 16-31 = 0
    for (int idx = tid; idx < 4096; idx += 256) {
        const int m = idx >> 7, c4 = idx & 127;
        __half2 p0 = __float2half2_rn(0.f), p1 = p0;
        if (m < 16) {
            const float* src = (m < 8) ? (Winit_h + (size_t)(u0 + m) * 512)
                                       : (Winit_c + (size_t)(u0 + m - 8) * 512);
            float4 v = *(const float4*)(src + c4 * 4);
            p0 = __floats2half2_rn(v.x, v.y);
            p1 = __floats2half2_rn(v.z, v.w);
        }
        *(__half2*)(sW + m * STRH + c4 * 4)     = p0;
        *(__half2*)(sW + m * STRH + c4 * 4 + 2) = p1;
    }
    for (int idx = tid; idx < 8192; idx += 256) {
        const int row = idx >> 7, c4 = idx & 127;
        float4 v = *(const float4*)(g_fmean + row * 512 + c4 * 4);
        *(__half2*)(sH + row * STRH + c4 * 4)     = __floats2half2_rn(v.x, v.y);
        *(__half2*)(sH + row * STRH + c4 * 4 + 2) = __floats2half2_rn(v.z, v.w);
    }
    __syncthreads();

    float acc[2][4];
    #pragma unroll
    for (int mt = 0; mt < 2; mt++)
        #pragma unroll
        for (int j = 0; j < 4; j++) acc[mt][j] = 0.f;
    #pragma unroll
    for (int kt2 = 0; kt2 < 16; kt2++) {
        uint32_t a0[2][4], a1[2][4], tb[4];
        #pragma unroll
        for (int mt = 0; mt < 2; mt++) {
            const uint32_t ro = aOff + mt * 16 * (STRH * 2) + kt2 * 64;
            ldm_x4(a0[mt], sWb + ro);
            ldm_x4(a1[mt], sWb + ro + 32);
        }
        ldm_x4(tb, sHb + bOff + kt2 * 64);
        uint32_t b0v[2] = {tb[0], tb[1]}, b1v[2] = {tb[2], tb[3]};
        #pragma unroll
        for (int mt = 0; mt < 2; mt++) {
            mma_fp16(acc[mt], a0[mt], b0v);
            mma_fp16(acc[mt], a1[mt], b1v);
        }
    }
    const int b0i = w * 8 + q * 2;
    // lane holds: h0 = acc[0][0..1], c0 = acc[0][2..3] for (u0+r, batches b0i,b0i+1)
    float c2[2] = {acc[0][2], acc[0][3]};
    g_hb16[0][b0i * 512 + u0 + r]       = __float2half_rn(acc[0][0]);
    g_hb16[0][(b0i + 1) * 512 + u0 + r] = __float2half_rn(acc[0][1]);
    __syncthreads();

    // ---- steady-state weights: sW row m = Whh[(m>>3)*512 + u0 + (m&7)]
    for (int idx = tid; idx < 4096; idx += 256) {
        const int m = idx >> 7, c4 = idx & 127;
        const int grow = (m >> 3) * 512 + u0 + (m & 7);
        float4 v = *(const float4*)(Whh + (size_t)grow * 512 + c4 * 4);
        *(__half2*)(sW + m * STRH + c4 * 4)     = __floats2half2_rn(v.x, v.y);
        *(__half2*)(sW + m * STRH + c4 * 4 + 2) = __floats2half2_rn(v.z, v.w);
    }

    // gpre column offsets: gate g -> g*512 + u0 + r
    float gp[8];
    {
        const float* gr = g_gpre;
        #pragma unroll
        for (int gci = 0; gci < 4; gci++) {
            const int col = gci * 512 + u0 + r;
            gp[gci * 2 + 0] = gr[(size_t)b0i * G4 + col];
            gp[gci * 2 + 1] = gr[(size_t)(b0i + 1) * G4 + col];
        }
    }
    gbar();

    for (int t = 0; t < TT; t++) {
        {
            const uint4* src = (const uint4*)g_hb16[t & 1];
            for (int idx = tid; idx < 4096; idx += 256) {
                const int row = idx >> 6, c8 = idx & 63;
                *(uint4*)(sH + row * STRH + c8 * 8) = src[row * 64 + c8];
            }
        }
        __syncthreads();

        acc[0][0] = gp[0]; acc[0][1] = gp[1]; acc[0][2] = gp[2]; acc[0][3] = gp[3];
        acc[1][0] = gp[4]; acc[1][1] = gp[5]; acc[1][2] = gp[6]; acc[1][3] = gp[7];
        #pragma unroll
        for (int kt2 = 0; kt2 < 16; kt2++) {
            uint32_t a0[2][4], a1[2][4], tb[4];
            #pragma unroll
            for (int mt = 0; mt < 2; mt++) {
                const uint32_t ro = aOff + mt * 16 * (STRH * 2) + kt2 * 64;
                ldm_x4(a0[mt], sWb + ro);
                ldm_x4(a1[mt], sWb + ro + 32);
            }
            ldm_x4(tb, sHb + bOff + kt2 * 64);
            uint32_t b0v[2] = {tb[0], tb[1]}, b1v[2] = {tb[2], tb[3]};
            #pragma unroll
            for (int mt = 0; mt < 2; mt++) {
                mma_fp16(acc[mt], a0[mt], b0v);
                mma_fp16(acc[mt], a1[mt], b1v);
            }
        }

        // shuffle-free cell update: i=acc[0][ii], f=acc[0][2+ii], g=acc[1][ii], o=acc[1][2+ii]
        #pragma unroll
        for (int ii = 0; ii < 2; ii++) {
            const float gi = acc[0][ii];
            const float gf = acc[0][2 + ii];
            const float gg = acc[1][ii];
            const float go = acc[1][2 + ii];
            const float si = 1.f / (1.f + __expf(-gi));
            const float sf = 1.f / (1.f + __expf(-gf));
            const float so = 1.f / (1.f + __expf(-go));
            c2[ii] = sf * c2[ii] + si * tanhf(gg);
            const float hnew = so * tanhf(c2[ii]);
            const __half hh = __float2half_rn(hnew);
            const int b = b0i + ii;
            g_hb16[(t + 1) & 1][b * 512 + u0 + r] = hh;
            g_hall[(size_t)(t * 64 + b) * 512 + u0 + r] = hh;
        }

        if (t < TT - 1) {
            const float* gr = g_gpre + (size_t)(t + 1) * BB * G4;
            #pragma unroll
            for (int gci = 0; gci < 4; gci++) {
                const int col = gci * 512 + u0 + r;
                gp[gci * 2 + 0] = gr[(size_t)b0i * G4 + col];
                gp[gci * 2 + 1] = gr[(size_t)(b0i + 1) * G4 + col];
            }
            gbar();
        }
    }
}

// ---------------- fused log_softmax + softmax, 512 threads/row ----------------
__global__ void __launch_bounds__(512) softmax_kernel(float* __restrict__ out) {
    const int r = blockIdx.x;
    const float4* x4 = (const float4*)(g_words + (size_t)r * VOC);
    float4* ols = (float4*)(out + (size_t)r * VOC);
    float4* osm = (float4*)(out + (size_t)TT * BB * VOC + (size_t)r * VOC);

    float m = -3.0e38f, s = 0.f;
    for (int i = threadIdx.x; i < VOC / 4; i += 512) {
        float4 v = x4[i];
        float m4 = fmaxf(fmaxf(v.x, v.y), fmaxf(v.z, v.w));
        float mn = fmaxf(m, m4);
        s = s * __expf(m - mn) + __expf(v.x - mn) + __expf(v.y - mn)
                               + __expf(v.z - mn) + __expf(v.w - mn);
        m = mn;
    }
    #pragma unroll
    for (int o = 16; o; o >>= 1) {
        float m2 = __shfl_down_sync(0xffffffffu, m, o);
        float s2 = __shfl_down_sync(0xffffffffu, s, o);
        float mx = fmaxf(m, m2);
        s = s * __expf(m - mx) + s2 * __expf(m2 - mx);
        m = mx;
    }
    __shared__ float sm[16], ss[16];
    __shared__ float bM, bS;
    const int wid = threadIdx.x >> 5, lane = threadIdx.x & 31;
    if (!lane) { sm[wid] = m; ss[wid] = s; }
    __syncthreads();
    if (threadIdx.x == 0) {
        float M = sm[0], S = ss[0];
        #pragma unroll
        for (int i = 1; i < 16; i++) {
            float mx = fmaxf(M, sm[i]);
            S = S * __expf(M - mx) + ss[i] * __expf(sm[i] - mx);
            M = mx;
        }
        bM = M; bS = S;
    }
    __syncthreads();
    const float M = bM;
    const float Sinv = 1.f / bS;
    const float lg = __logf(bS);
    for (int i = threadIdx.x; i < VOC / 4; i += 512) {
        float4 v = x4[i];
        float4 l4, p4;
        l4.x = v.x - M - lg; p4.x = __expf(v.x - M) * Sinv;
        l4.y = v.y - M - lg; p4.y = __expf(v.y - M) * Sinv;
        l4.z = v.z - M - lg; p4.z = __expf(v.z - M) * Sinv;
        l4.w = v.w - M - lg; p4.w = __expf(v.w - M) * Sinv;
        ols[i] = l4;
        osm[i] = p4;
    }
}

// ---------------- launch ----------------
extern "C" void kernel_launch(void* const* d_in, const int* in_sizes, int n_in,
                              void* d_out, int out_size) {
    (void)in_sizes; (void)n_in; (void)out_size;
    const float* features = (const float*)d_in[0];
    const int*   captions = (const int*)  d_in[1];
    const float* W_init_h = (const float*)d_in[2];
    const float* W_init_c = (const float*)d_in[3];
    const float* W_av     = (const float*)d_in[4];
    // d_in[5] b_av, d_in[6] W_ah, d_in[7] b_ah : dead (softmax shift-invariance)
    const float* embed    = (const float*)d_in[8];
    const float* W_ih     = (const float*)d_in[9];
    const float* W_hh     = (const float*)d_in[10];
    const float* b_ih     = (const float*)d_in[11];
    const float* b_hh     = (const float*)d_in[12];
    const float* W_out    = (const float*)d_in[13];
    const float* b_out    = (const float*)d_in[14];
    float* out = (float*)d_out;

    float *gpre, *words;
    __half *wout16, *wih16, *a16, *hall;
    cudaGetSymbolAddress((void**)&gpre,   g_gpre);
    cudaGetSymbolAddress((void**)&words,  g_words);
    cudaGetSymbolAddress((void**)&wout16, g_Wout16);
    cudaGetSymbolAddress((void**)&wih16,  g_Wih16);
    cudaGetSymbolAddress((void**)&a16,    g_A16);
    cudaGetSymbolAddress((void**)&hall,   g_hall);

    // lazy one-time setup (outside graph capture: first call is the correctness run)
    static bool init_done = false;
    static cudaStream_t sB;
    static cudaEvent_t evFork, evWout;
    if (!init_done) {
        cudaFuncSetAttribute(lstm_kernel, cudaFuncAttributeMaxDynamicSharedMemorySize,
                             (32 + 64) * STRH * 2);
        cudaFuncSetAttribute(gemm_mma, cudaFuncAttributeMaxDynamicSharedMemorySize, 2 * STAGEB);
        cudaStreamCreateWithFlags(&sB, cudaStreamNonBlocking);
        cudaEventCreateWithFlags(&evFork, cudaEventDisableTiming);
        cudaEventCreateWithFlags(&evWout, cudaEventDisableTiming);
        init_done = true;
    }
    const int LSTM_SMEM = (32 + 64) * STRH * 2;       // 99840 B
    const int GEMM_SMEM = 2 * STAGEB;                 // 40960 B

    // fork: W_out conversion runs concurrently with the attention/gpre/LSTM chain
    cudaEventRecord(evFork, 0);
    cudaStreamWaitEvent(sB, evFork, 0);
    cvt_hi8<<<(VOC * 512 / 8 + 255) / 256, 256, 0, sB>>>(W_out, wout16, VOC * 512);
    cudaEventRecord(evWout, sB);

    // attention: logits (896 blocks), fused ctx+fmean+softmax-weights (512 blocks)
    attn_dot<<<dim3(BB, 14), 256>>>(features, W_av);
    attn_ctx<<<dim3(BB, 8), 512>>>(features);

    // concat A (rowmap inline) + W_ih conversion
    cvt_concat8<<<(TT * BB * 1024 / 8 + 255) / 256, 256>>>(embed, captions);
    cvt_hi8<<<(G4 * 1024 / 8 + 255) / 256, 256>>>(W_ih, wih16, G4 * 1024);

    // gpre = [ctx|emb] @ W_ih^T + b_ih + b_hh   (K=1024)
    gemm_mma<<<dim3(TT * BB / 128, G4 / 128), 256, GEMM_SMEM>>>(
        a16, wih16, gpre, G4, G4, 1024, b_ih, b_hh);

    // persistent HMMA LSTM (64 blocks, 8 u-dims each)
    lstm_kernel<<<NBLK, 256, LSTM_SMEM>>>(W_init_h, W_init_c, W_hh);

    // join W_out conversion, then monolithic words GEMM (full-chip, grid 10x79)
    cudaStreamWaitEvent(0, evWout, 0);
    gemm_mma<<<dim3(TT * BB / 128, (VOC + 127) / 128), 256, GEMM_SMEM>>>(
        hall, wout16, words, VOC, VOC, 512, b_out, nullptr);

    // fused log_softmax + softmax (single launch)
    softmax_kernel<<<TT * BB, 512>>>(out);
}

// round 15
// speedup vs baseline: 1.0649x; 1.0649x over previous
#include <cuda_runtime.h>
#include <cuda_fp16.h>
#include <cstdint>
#include <cstddef>

#define TT   20
#define BB   64
#define NNF  196
#define VOC  10000
#define G4   2048
#define NBLK 128          // persistent LSTM grid

// ---------------- static device scratch ----------------
__device__ float g_fmean[BB * 512];
__device__ float g_ctx  [BB * 512];
__device__ float g_attl [BB * NNF];
__device__ float g_gpre [TT * BB * G4];
__device__ float g_words[TT * BB * VOC];
__device__ unsigned long long g_bar;   // monotonic across replays

__device__ __half g_Wout16[VOC * 512];
__device__ __half g_Wih16 [G4 * 1024];
__device__ __half g_A16   [TT * BB * 1024];
__device__ __half g_hall  [TT * BB * 512];
__device__ __half g_hb16  [2][BB * 512];

// ---------------- helpers ----------------
__device__ __forceinline__ uint32_t smem_u32(const void* p) {
    uint32_t a;
    asm("{ .reg .u64 t; cvta.to.shared.u64 t, %1; cvt.u32.u64 %0, t; }"
        : "=r"(a) : "l"(p));
    return a;
}
__device__ __forceinline__ void ldm_x4(uint32_t* r, uint32_t addr) {
    asm volatile("ldmatrix.sync.aligned.m8n8.x4.shared.b16 {%0,%1,%2,%3}, [%4];"
                 : "=r"(r[0]), "=r"(r[1]), "=r"(r[2]), "=r"(r[3]) : "r"(addr));
}
__device__ __forceinline__ void mma_fp16(float* d, const uint32_t* a, const uint32_t* b) {
    asm volatile(
        "mma.sync.aligned.m16n8k16.row.col.f32.f16.f16.f32 "
        "{%0,%1,%2,%3}, {%4,%5,%6,%7}, {%8,%9}, {%0,%1,%2,%3};"
        : "+f"(d[0]), "+f"(d[1]), "+f"(d[2]), "+f"(d[3])
        : "r"(a[0]), "r"(a[1]), "r"(a[2]), "r"(a[3]), "r"(b[0]), "r"(b[1]));
}
__device__ __forceinline__ void cpa16(uint32_t dst, const void* src, int srcsz) {
    asm volatile("cp.async.cg.shared.global [%0], [%1], 16, %2;"
                 :: "r"(dst), "l"(src), "r"(srcsz));
}
__device__ __forceinline__ void cpa_commit() {
    asm volatile("cp.async.commit_group;");
}
template<int NG> __device__ __forceinline__ void cpa_wait() {
    asm volatile("cp.async.wait_group %0;" :: "n"(NG));
}

// ============ single-pass fp16 GEMM: C[m,n] = sum_k A[m,k]*B[n,k] ==========
// BM=128, BN=128, BK=32; 8 warps (4x2); warp tile 32x64.
#define ASTR 40                         // padded fp16 row stride (80B)
#define BUFB (128 * ASTR * 2)           // one operand buffer: 10240 bytes
#define STAGEB (2 * BUFB)               // A|B per stage: 20480 bytes

__global__ void __launch_bounds__(256) gemm_mma(
    const __half* __restrict__ A, const __half* __restrict__ B,
    float* __restrict__ C, int N, int ldc, int K,
    const float* __restrict__ bias0, const float* __restrict__ bias1)
{
    extern __shared__ __align__(16) __half dsm[];
    const uint32_t smb = smem_u32(dsm);

    const int tid  = threadIdx.x;
    const int lane = tid & 31;
    const int w    = tid >> 5;
    const int wm   = w >> 1;
    const int wn   = w & 1;
    const int m0   = blockIdx.x * 128;
    const int n0   = blockIdx.y * 128;
    const int mbase = wm * 32;
    const int nbase = wn * 64;
    const int g = lane >> 2;
    const int q = lane & 3;

    const int i0 = tid, i1 = tid + 256;
    const int r0s = i0 >> 2, k0s = (i0 & 3) * 8;
    const int r1s = i1 >> 2, k1s = (i1 & 3) * 8;
    const int bsz0 = (n0 + r0s) < N ? 16 : 0;
    const int bsz1 = (n0 + r1s) < N ? 16 : 0;
    const uint32_t d0 = (uint32_t)(r0s * ASTR + k0s) * 2;
    const uint32_t d1 = (uint32_t)(r1s * ASTR + k1s) * 2;

    const int l7 = lane & 7;
    const uint32_t aRow = mbase + l7 + ((lane >> 3) & 1) * 8;
    const uint32_t aKof = (lane >> 4) * 16;
    const uint32_t bRow = nbase + l7 + (lane >> 4) * 8;
    const uint32_t bKof = ((lane >> 3) & 1) * 16;

    float acc[2][8][4];
    #pragma unroll
    for (int mt = 0; mt < 2; mt++)
        #pragma unroll
        for (int nt = 0; nt < 8; nt++)
            #pragma unroll
            for (int r = 0; r < 4; r++) acc[mt][nt][r] = 0.f;

    const int nk = K / 32;

    auto load_stage = [&](int kt, int s) {
        const int k0 = kt * 32;
        const uint32_t sb = smb + (uint32_t)s * STAGEB;
        cpa16(sb + d0,        A + (size_t)(m0 + r0s) * K + k0 + k0s, 16);
        cpa16(sb + d1,        A + (size_t)(m0 + r1s) * K + k0 + k1s, 16);
        cpa16(sb + BUFB + d0, B + (size_t)(n0 + r0s) * K + k0 + k0s, bsz0);
        cpa16(sb + BUFB + d1, B + (size_t)(n0 + r1s) * K + k0 + k1s, bsz1);
        cpa_commit();
    };

    load_stage(0, 0);

    for (int kt = 0; kt < nk; kt++) {
        if (kt + 1 < nk) load_stage(kt + 1, (kt + 1) & 1);
        if (kt + 1 < nk) cpa_wait<1>(); else cpa_wait<0>();
        __syncthreads();

        const uint32_t sb = smb + (uint32_t)(kt & 1) * STAGEB;
        const uint32_t bA = sb, bB = sb + BUFB;

        #pragma unroll
        for (int kk = 0; kk < 2; kk++) {
            const uint32_t kb = kk * 32;
            uint32_t ah[2][4];
            #pragma unroll
            for (int mt = 0; mt < 2; mt++) {
                const uint32_t ro = (aRow + mt * 16) * (ASTR * 2) + kb + aKof;
                ldm_x4(ah[mt], bA + ro);
            }
            #pragma unroll
            for (int np = 0; np < 4; np++) {
                const uint32_t ro = (bRow + np * 16) * (ASTR * 2) + kb + bKof;
                uint32_t tb[4];
                ldm_x4(tb, bB + ro);
                uint32_t bh0[2] = {tb[0], tb[1]}, bh1[2] = {tb[2], tb[3]};
                #pragma unroll
                for (int mt = 0; mt < 2; mt++) {
                    mma_fp16(acc[mt][np * 2 + 0], ah[mt], bh0);
                    mma_fp16(acc[mt][np * 2 + 1], ah[mt], bh1);
                }
            }
        }
        __syncthreads();
    }

    #pragma unroll
    for (int mt = 0; mt < 2; mt++) {
        #pragma unroll
        for (int nt = 0; nt < 8; nt++) {
            const int n = n0 + nbase + nt * 8 + q * 2;
            if (n < N) {
                #pragma unroll
                for (int half = 0; half < 2; half++) {
                    const int m = m0 + mbase + mt * 16 + g + half * 8;
                    float v0 = acc[mt][nt][half * 2 + 0];
                    float v1 = acc[mt][nt][half * 2 + 1];
                    if (bias0) { v0 += bias0[n]; v1 += bias0[n + 1]; }
                    if (bias1) { v0 += bias1[n]; v1 += bias1[n + 1]; }
                    *(float2*)(C + (size_t)m * ldc + n) = make_float2(v0, v1);
                }
            }
        }
    }
}

// ---------------- fp32 -> fp16, 8 elems/thread ----------------
__global__ void __launch_bounds__(256) cvt_hi8(
    const float* __restrict__ src, __half* __restrict__ hi, int total)
{
    const int i = (blockIdx.x * 256 + threadIdx.x) * 8;
    if (i < total) {
        float4 x0 = *(const float4*)(src + i);
        float4 x1 = *(const float4*)(src + i + 4);
        float xs[8] = {x0.x, x0.y, x0.z, x0.w, x1.x, x1.y, x1.z, x1.w};
        __half h8[8];
        #pragma unroll
        for (int j = 0; j < 8; j++) h8[j] = __float2half_rn(xs[j]);
        *(uint4*)(hi + i) = *(const uint4*)h8;
    }
}

// ---------------- concat A = [ctx(b) | embed(tok)] fp16 (rowmap inline) ------
__global__ void __launch_bounds__(256) cvt_concat8(const float* __restrict__ embed,
                                                   const int* __restrict__ captions) {
    const int i = (blockIdx.x * 256 + threadIdx.x) * 8;
    if (i < TT * BB * 1024) {
        const int r = i >> 10, k = i & 1023;
        const int b = r & 63, t = r >> 6;
        const float* sp;
        if (k < 512) {
            sp = g_ctx + b * 512 + k;
        } else {
            const int tok = captions[b * TT + t];
            sp = embed + (size_t)tok * 512 + (k - 512);
        }
        float4 x0 = *(const float4*)sp;
        float4 x1 = *(const float4*)(sp + 4);
        float xs[8] = {x0.x, x0.y, x0.z, x0.w, x1.x, x1.y, x1.z, x1.w};
        __half h8[8];
        #pragma unroll
        for (int j = 0; j < 8; j++) h8[j] = __float2half_rn(xs[j]);
        *(uint4*)(g_A16 + i) = *(const uint4*)h8;
    }
}

// ---------------- attention logits (parallel, 896 blocks) ----------------
__global__ void __launch_bounds__(256) attn_dot(const float* __restrict__ features,
                                                const float* __restrict__ W_av) {
    const int b   = blockIdx.x;
    const int n0  = blockIdx.y * 14;
    __shared__ float sW[512];
    const int tid = threadIdx.x;
    const int wid = tid >> 5, lane = tid & 31;
    for (int i = tid; i < 512; i += 256) sW[i] = W_av[i];
    __syncthreads();

    const float* fb = features + (size_t)b * NNF * 512;
    for (int n = n0 + wid; n < n0 + 14 && n < NNF; n += 8) {
        const float* fr = fb + (size_t)n * 512;
        float s0 = 0.f, s1 = 0.f, s2 = 0.f, s3 = 0.f;
        #pragma unroll
        for (int i = 0; i < 4; i++) {
            const int o = lane + i * 128;
            s0 = fmaf(fr[o],      sW[o],      s0);
            s1 = fmaf(fr[o + 32], sW[o + 32], s1);
            s2 = fmaf(fr[o + 64], sW[o + 64], s2);
            s3 = fmaf(fr[o + 96], sW[o + 96], s3);
        }
        float s = (s0 + s1) + (s2 + s3);
        #pragma unroll
        for (int o = 16; o; o >>= 1) s += __shfl_down_sync(0xffffffffu, s, o);
        if (!lane) g_attl[b * NNF + n] = s;
    }
}

// ------- ctx + fmean with fused softmax weights: grid (BB, 8), 512 thr -------
__global__ void __launch_bounds__(512) attn_ctx(const float* __restrict__ features) {
    const int b  = blockIdx.x;
    const int v0 = blockIdx.y * 64;
    const int tid = threadIdx.x;
    const int c  = tid & 63;
    const int rg = tid >> 6;          // 0..7, rows rg*25..+24
    __shared__ float sw[NNF];
    __shared__ float sred[16];
    __shared__ float sM, sI;
    __shared__ float pac[8][64];
    __shared__ float pam[8][64];
    const int wid = tid >> 5, lane = tid & 31;

    float m = -3.0e38f;
    if (tid < NNF) { m = g_attl[b * NNF + tid]; sw[tid] = m; }
    #pragma unroll
    for (int o = 16; o; o >>= 1) m = fmaxf(m, __shfl_down_sync(0xffffffffu, m, o));
    if (!lane) sred[wid] = m;
    __syncthreads();
    if (tid == 0) {
        float mm = sred[0];
        #pragma unroll
        for (int i = 1; i < 16; i++) mm = fmaxf(mm, sred[i]);
        sM = mm;
    }
    __syncthreads();
    float e = 0.f;
    if (tid < NNF) { e = __expf(sw[tid] - sM); sw[tid] = e; }
    float s = e;
    #pragma unroll
    for (int o = 16; o; o >>= 1) s += __shfl_down_sync(0xffffffffu, s, o);
    if (!lane) sred[wid] = s;
    __syncthreads();
    if (tid == 0) {
        float ss = 0.f;
        #pragma unroll
        for (int i = 0; i < 16; i++) ss += sred[i];
        sI = 1.f / ss;
    }
    __syncthreads();
    const float inv = sI;

    const float* fp = features + (size_t)b * NNF * 512 + v0 + c;
    float ac = 0.f, am = 0.f;
    const int nb = rg * 25;
    #pragma unroll 5
    for (int j = 0; j < 25; j++) {
        const int n = nb + j;
        if (n < NNF) {
            const float f = fp[(size_t)n * 512];
            ac = fmaf(sw[n], f, ac);
            am += f;
        }
    }
    pac[rg][c] = ac;
    pam[rg][c] = am;
    __syncthreads();
    if (rg == 0) {
        float a = 0.f, mm = 0.f;
        #pragma unroll
        for (int i = 0; i < 8; i++) { a += pac[i][c]; mm += pam[i][c]; }
        g_ctx  [b * 512 + v0 + c] = a * inv;
        g_fmean[b * 512 + v0 + c] = mm * (1.f / (float)NNF);
    }
}

// ================= persistent HMMA LSTM (phase0 + 20 steps, 1 launch) =========
__device__ __forceinline__ void gbar() {
    __syncthreads();
    if (threadIdx.x == 0) {
        unsigned long long old;
        asm volatile("atom.release.gpu.global.add.u64 %0, [%1], %2;"
                     : "=l"(old) : "l"(&g_bar), "l"(1ULL) : "memory");
        unsigned long long tgt = old - (old & (unsigned long long)(NBLK - 1)) + (unsigned long long)NBLK;
        unsigned long long cur;
        do {
            asm volatile("ld.global.acquire.gpu.u64 %0, [%1];" : "=l"(cur) : "l"(&g_bar));
        } while (cur < tgt);
    }
    __syncthreads();
}

#define STRH 520   // fp16 row stride for sW/sH (1040 B, conflict-free ldmatrix)

__global__ void __launch_bounds__(256, 1) lstm_kernel(
    const float* __restrict__ Winit_h, const float* __restrict__ Winit_c,
    const float* __restrict__ Whh)
{
    extern __shared__ __half smh[];
    __half* sW = smh;                 // [16][STRH]  gate-row weights
    __half* sH = smh + 16 * STRH;     // [64][STRH]  h (fp16)

    const int tid  = threadIdx.x;
    const int w    = tid >> 5;
    const int lane = tid & 31;
    const int l7   = lane & 7;
    const int r    = lane >> 2;       // 0..7
    const int q    = lane & 3;
    const int u0   = blockIdx.x * 4;

    const uint32_t sWb = smem_u32(sW);
    const uint32_t sHb = smem_u32(sH);
    const uint32_t aOff = (uint32_t)((l7 + ((lane >> 3) & 1) * 8) * (STRH * 2) + (lane >> 4) * 16);
    const uint32_t bOff = (uint32_t)((w * 8 + l7) * (STRH * 2) + (lane >> 3) * 16);

    // ---- phase 0: sW rows 0-3 = Winit_h[u0+j], 4-7 = Winit_c[u0+j], 8-15 = 0
    for (int idx = tid; idx < 2048; idx += 256) {
        const int m = idx >> 7, c4 = idx & 127;
        __half2 p0 = __float2half2_rn(0.f), p1 = p0;
        if (m < 8) {
            const float* src = (m < 4) ? (Winit_h + (size_t)(u0 + m) * 512)
                                       : (Winit_c + (size_t)(u0 + m - 4) * 512);
            float4 v = *(const float4*)(src + c4 * 4);
            p0 = __floats2half2_rn(v.x, v.y);
            p1 = __floats2half2_rn(v.z, v.w);
        }
        *(__half2*)(sW + m * STRH + c4 * 4)     = p0;
        *(__half2*)(sW + m * STRH + c4 * 4 + 2) = p1;
    }
    for (int idx = tid; idx < 8192; idx += 256) {
        const int row = idx >> 7, c4 = idx & 127;
        float4 v = *(const float4*)(g_fmean + row * 512 + c4 * 4);
        *(__half2*)(sH + row * STRH + c4 * 4)     = __floats2half2_rn(v.x, v.y);
        *(__half2*)(sH + row * STRH + c4 * 4 + 2) = __floats2half2_rn(v.z, v.w);
    }
    __syncthreads();

    float acc[4] = {0.f, 0.f, 0.f, 0.f};
    #pragma unroll
    for (int kt2 = 0; kt2 < 16; kt2++) {
        uint32_t a0[4], a1[4], tb[4];
        ldm_x4(a0, sWb + aOff + kt2 * 64);
        ldm_x4(a1, sWb + aOff + kt2 * 64 + 32);
        ldm_x4(tb, sHb + bOff + kt2 * 64);
        uint32_t b0v[2] = {tb[0], tb[1]}, b1v[2] = {tb[2], tb[3]};
        mma_fp16(acc, a0, b0v);
        mma_fp16(acc, a1, b1v);
    }
    const int b0i = w * 8 + q * 2;
    float c2[2] = {0.f, 0.f};
    {
        const float cc0 = __shfl_xor_sync(0xffffffffu, acc[0], 16);
        const float cc1 = __shfl_xor_sync(0xffffffffu, acc[1], 16);
        if (lane < 16) {
            c2[0] = cc0; c2[1] = cc1;
            g_hb16[0][b0i * 512 + u0 + r]       = __float2half_rn(acc[0]);
            g_hb16[0][(b0i + 1) * 512 + u0 + r] = __float2half_rn(acc[1]);
        }
    }
    __syncthreads();

    // ---- steady-state weights: sW row m = Whh[(m>>2)*512 + u0 + (m&3)]
    for (int idx = tid; idx < 2048; idx += 256) {
        const int m = idx >> 7, c4 = idx & 127;
        const int grow = (m >> 2) * 512 + u0 + (m & 3);
        float4 v = *(const float4*)(Whh + (size_t)grow * 512 + c4 * 4);
        *(__half2*)(sW + m * STRH + c4 * 4)     = __floats2half2_rn(v.x, v.y);
        *(__half2*)(sW + m * STRH + c4 * 4 + 2) = __floats2half2_rn(v.z, v.w);
    }

    const int m1 = r, m2 = r + 8;
    const int col1 = (m1 >> 2) * 512 + u0 + (m1 & 3);
    const int col2 = (m2 >> 2) * 512 + u0 + (m2 & 3);
    float gp[4];
    {
        const float* gr = g_gpre;
        gp[0] = gr[(size_t)b0i * G4 + col1];
        gp[1] = gr[(size_t)(b0i + 1) * G4 + col1];
        gp[2] = gr[(size_t)b0i * G4 + col2];
        gp[3] = gr[(size_t)(b0i + 1) * G4 + col2];
    }
    gbar();

    for (int t = 0; t < TT; t++) {
        {
            const uint4* src = (const uint4*)g_hb16[t & 1];
            for (int idx = tid; idx < 4096; idx += 256) {
                const int row = idx >> 6, c8 = idx & 63;
                *(uint4*)(sH + row * STRH + c8 * 8) = src[row * 64 + c8];
            }
        }
        __syncthreads();

        acc[0] = gp[0]; acc[1] = gp[1]; acc[2] = gp[2]; acc[3] = gp[3];
        #pragma unroll
        for (int kt2 = 0; kt2 < 16; kt2++) {
            uint32_t a0[4], a1[4], tb[4];
            ldm_x4(a0, sWb + aOff + kt2 * 64);
            ldm_x4(a1, sWb + aOff + kt2 * 64 + 32);
            ldm_x4(tb, sHb + bOff + kt2 * 64);
            uint32_t b0v[2] = {tb[0], tb[1]}, b1v[2] = {tb[2], tb[3]};
            mma_fp16(acc, a0, b0v);
            mma_fp16(acc, a1, b1v);
        }

        const float f0 = __shfl_xor_sync(0xffffffffu, acc[0], 16);
        const float f1 = __shfl_xor_sync(0xffffffffu, acc[1], 16);
        const float o0 = __shfl_xor_sync(0xffffffffu, acc[2], 16);
        const float o1 = __shfl_xor_sync(0xffffffffu, acc[3], 16);
        if (lane < 16) {
            #pragma unroll
            for (int ii = 0; ii < 2; ii++) {
                const float gi = acc[ii];
                const float gg = acc[2 + ii];
                const float gf = ii ? f1 : f0;
                const float go = ii ? o1 : o0;
                const float si = 1.f / (1.f + __expf(-gi));
                const float sf = 1.f / (1.f + __expf(-gf));
                const float so = 1.f / (1.f + __expf(-go));
                c2[ii] = sf * c2[ii] + si * tanhf(gg);
                const float hnew = so * tanhf(c2[ii]);
                const __half hh = __float2half_rn(hnew);
                const int b = b0i + ii;
                g_hb16[(t + 1) & 1][b * 512 + u0 + r] = hh;
                g_hall[(size_t)(t * 64 + b) * 512 + u0 + r] = hh;
            }
        }

        if (t < TT - 1) {
            const float* gr = g_gpre + (size_t)(t + 1) * BB * G4;
            gp[0] = gr[(size_t)b0i * G4 + col1];
            gp[1] = gr[(size_t)(b0i + 1) * G4 + col1];
            gp[2] = gr[(size_t)b0i * G4 + col2];
            gp[3] = gr[(size_t)(b0i + 1) * G4 + col2];
            gbar();
        }
    }
}

// ---------------- fused log_softmax + softmax, 512 threads/row ----------------
__global__ void __launch_bounds__(512) softmax_kernel(float* __restrict__ out) {
    const int r = blockIdx.x;
    const float4* x4 = (const float4*)(g_words + (size_t)r * VOC);
    float4* ols = (float4*)(out + (size_t)r * VOC);
    float4* osm = (float4*)(out + (size_t)TT * BB * VOC + (size_t)r * VOC);

    float m = -3.0e38f, s = 0.f;
    for (int i = threadIdx.x; i < VOC / 4; i += 512) {
        float4 v = x4[i];
        float m4 = fmaxf(fmaxf(v.x, v.y), fmaxf(v.z, v.w));
        float mn = fmaxf(m, m4);
        s = s * __expf(m - mn) + __expf(v.x - mn) + __expf(v.y - mn)
                               + __expf(v.z - mn) + __expf(v.w - mn);
        m = mn;
    }
    #pragma unroll
    for (int o = 16; o; o >>= 1) {
        float m2 = __shfl_down_sync(0xffffffffu, m, o);
        float s2 = __shfl_down_sync(0xffffffffu, s, o);
        float mx = fmaxf(m, m2);
        s = s * __expf(m - mx) + s2 * __expf(m2 - mx);
        m = mx;
    }
    __shared__ float sm[16], ss[16];
    __shared__ float bM, bS;
    const int wid = threadIdx.x >> 5, lane = threadIdx.x & 31;
    if (!lane) { sm[wid] = m; ss[wid] = s; }
    __syncthreads();
    if (threadIdx.x == 0) {
        float M = sm[0], S = ss[0];
        #pragma unroll
        for (int i = 1; i < 16; i++) {
            float mx = fmaxf(M, sm[i]);
            S = S * __expf(M - mx) + ss[i] * __expf(sm[i] - mx);
            M = mx;
        }
        bM = M; bS = S;
    }
    __syncthreads();
    const float M = bM;
    const float Sinv = 1.f / bS;
    const float lg = __logf(bS);
    for (int i = threadIdx.x; i < VOC / 4; i += 512) {
        float4 v = x4[i];
        float4 l4, p4;
        l4.x = v.x - M - lg; p4.x = __expf(v.x - M) * Sinv;
        l4.y = v.y - M - lg; p4.y = __expf(v.y - M) * Sinv;
        l4.z = v.z - M - lg; p4.z = __expf(v.z - M) * Sinv;
        l4.w = v.w - M - lg; p4.w = __expf(v.w - M) * Sinv;
        ols[i] = l4;
        osm[i] = p4;
    }
}

// ---------------- launch ----------------
extern "C" void kernel_launch(void* const* d_in, const int* in_sizes, int n_in,
                              void* d_out, int out_size) {
    (void)in_sizes; (void)n_in; (void)out_size;
    const float* features = (const float*)d_in[0];
    const int*   captions = (const int*)  d_in[1];
    const float* W_init_h = (const float*)d_in[2];
    const float* W_init_c = (const float*)d_in[3];
    const float* W_av     = (const float*)d_in[4];
    // d_in[5] b_av, d_in[6] W_ah, d_in[7] b_ah : dead (softmax shift-invariance)
    const float* embed    = (const float*)d_in[8];
    const float* W_ih     = (const float*)d_in[9];
    const float* W_hh     = (const float*)d_in[10];
    const float* b_ih     = (const float*)d_in[11];
    const float* b_hh     = (const float*)d_in[12];
    const float* W_out    = (const float*)d_in[13];
    const float* b_out    = (const float*)d_in[14];
    float* out = (float*)d_out;

    float *gpre, *words;
    __half *wout16, *wih16, *a16, *hall;
    cudaGetSymbolAddress((void**)&gpre,   g_gpre);
    cudaGetSymbolAddress((void**)&words,  g_words);
    cudaGetSymbolAddress((void**)&wout16, g_Wout16);
    cudaGetSymbolAddress((void**)&wih16,  g_Wih16);
    cudaGetSymbolAddress((void**)&a16,    g_A16);
    cudaGetSymbolAddress((void**)&hall,   g_hall);

    // lazy one-time setup (outside graph capture: first call is the correctness run)
    static bool init_done = false;
    static cudaStream_t sB;
    static cudaEvent_t evFork, evWih, evWout;
    if (!init_done) {
        cudaFuncSetAttribute(lstm_kernel, cudaFuncAttributeMaxDynamicSharedMemorySize,
                             (16 + 64) * STRH * 2);
        cudaFuncSetAttribute(gemm_mma, cudaFuncAttributeMaxDynamicSharedMemorySize, 2 * STAGEB);
        cudaStreamCreateWithFlags(&sB, cudaStreamNonBlocking);
        cudaEventCreateWithFlags(&evFork, cudaEventDisableTiming);
        cudaEventCreateWithFlags(&evWih,  cudaEventDisableTiming);
        cudaEventCreateWithFlags(&evWout, cudaEventDisableTiming);
        init_done = true;
    }
    const int LSTM_SMEM = (16 + 64) * STRH * 2;       // 83200 B
    const int GEMM_SMEM = 2 * STAGEB;                 // 40960 B

    // fork: both weight conversions run on sB, overlapping the attention chain
    cudaEventRecord(evFork, 0);
    cudaStreamWaitEvent(sB, evFork, 0);
    cvt_hi8<<<(G4 * 1024 / 8 + 255) / 256, 256, 0, sB>>>(W_ih, wih16, G4 * 1024);
    cudaEventRecord(evWih, sB);
    cvt_hi8<<<(VOC * 512 / 8 + 255) / 256, 256, 0, sB>>>(W_out, wout16, VOC * 512);
    cudaEventRecord(evWout, sB);

    // attention: logits (896 blocks), fused ctx+fmean+softmax-weights (512 blocks)
    attn_dot<<<dim3(BB, 14), 256>>>(features, W_av);
    attn_ctx<<<dim3(BB, 8), 512>>>(features);

    // concat A (rowmap inline)
    cvt_concat8<<<(TT * BB * 1024 / 8 + 255) / 256, 256>>>(embed, captions);

    // gpre = [ctx|emb] @ W_ih^T + b_ih + b_hh   (K=1024), joins W_ih conversion
    cudaStreamWaitEvent(0, evWih, 0);
    gemm_mma<<<dim3(TT * BB / 128, G4 / 128), 256, GEMM_SMEM>>>(
        a16, wih16, gpre, G4, G4, 1024, b_ih, b_hh);

    // persistent HMMA LSTM
    lstm_kernel<<<NBLK, 256, LSTM_SMEM>>>(W_init_h, W_init_c, W_hh);

    // join W_out conversion, then monolithic words GEMM (full-chip, grid 10x79)
    cudaStreamWaitEvent(0, evWout, 0);
    gemm_mma<<<dim3(TT * BB / 128, (VOC + 127) / 128), 256, GEMM_SMEM>>>(
        hall, wout16, words, VOC, VOC, 512, b_out, nullptr);

    // fused log_softmax + softmax (single launch)
    softmax_kernel<<<TT * BB, 512>>>(out);
}

// round 16
// speedup vs baseline: 1.0719x; 1.0065x over previous
#include <cuda_runtime.h>
#include <cuda_fp16.h>
#include <cstdint>
#include <cstddef>

#define TT   20
#define BB   64
#define NNF  196
#define VOC  10000
#define G4   2048
#define NBLK 128          // persistent LSTM grid

// ---------------- static device scratch ----------------
__device__ float g_fmean[BB * 512];
__device__ float g_attl [BB * NNF];
__device__ float g_gpre [TT * BB * G4];
__device__ float g_words[TT * BB * VOC];
__device__ unsigned long long g_bar;   // monotonic across replays

__device__ __half g_Wout16[VOC * 512];
__device__ __half g_Wih16 [G4 * 1024];
__device__ __half g_A16   [TT * BB * 1024];
__device__ __half g_hall  [TT * BB * 512];
__device__ __half g_hb16  [2][BB * 512];

// ---------------- helpers ----------------
__device__ __forceinline__ uint32_t smem_u32(const void* p) {
    uint32_t a;
    asm("{ .reg .u64 t; cvta.to.shared.u64 t, %1; cvt.u32.u64 %0, t; }"
        : "=r"(a) : "l"(p));
    return a;
}
__device__ __forceinline__ void ldm_x4(uint32_t* r, uint32_t addr) {
    asm volatile("ldmatrix.sync.aligned.m8n8.x4.shared.b16 {%0,%1,%2,%3}, [%4];"
                 : "=r"(r[0]), "=r"(r[1]), "=r"(r[2]), "=r"(r[3]) : "r"(addr));
}
__device__ __forceinline__ void mma_fp16(float* d, const uint32_t* a, const uint32_t* b) {
    asm volatile(
        "mma.sync.aligned.m16n8k16.row.col.f32.f16.f16.f32 "
        "{%0,%1,%2,%3}, {%4,%5,%6,%7}, {%8,%9}, {%0,%1,%2,%3};"
        : "+f"(d[0]), "+f"(d[1]), "+f"(d[2]), "+f"(d[3])
        : "r"(a[0]), "r"(a[1]), "r"(a[2]), "r"(a[3]), "r"(b[0]), "r"(b[1]));
}
__device__ __forceinline__ void cpa16(uint32_t dst, const void* src, int srcsz) {
    asm volatile("cp.async.cg.shared.global [%0], [%1], 16, %2;"
                 :: "r"(dst), "l"(src), "r"(srcsz));
}
__device__ __forceinline__ void cpa_commit() {
    asm volatile("cp.async.commit_group;");
}
template<int NG> __device__ __forceinline__ void cpa_wait() {
    asm volatile("cp.async.wait_group %0;" :: "n"(NG));
}

// ============ single-pass fp16 GEMM: C[m,n] = sum_k A[m,k]*B[n,k] ==========
// BM=128, BN=128, BK=32; 8 warps (4x2); warp tile 32x64.
#define ASTR 40                         // padded fp16 row stride (80B)
#define BUFB (128 * ASTR * 2)           // one operand buffer: 10240 bytes
#define STAGEB (2 * BUFB)               // A|B per stage: 20480 bytes

__global__ void __launch_bounds__(256) gemm_mma(
    const __half* __restrict__ A, const __half* __restrict__ B,
    float* __restrict__ C, int N, int ldc, int K,
    const float* __restrict__ bias0, const float* __restrict__ bias1)
{
    extern __shared__ __align__(16) __half dsm[];
    const uint32_t smb = smem_u32(dsm);

    const int tid  = threadIdx.x;
    const int lane = tid & 31;
    const int w    = tid >> 5;
    const int wm   = w >> 1;
    const int wn   = w & 1;
    const int m0   = blockIdx.x * 128;
    const int n0   = blockIdx.y * 128;
    const int mbase = wm * 32;
    const int nbase = wn * 64;
    const int g = lane >> 2;
    const int q = lane & 3;

    const int i0 = tid, i1 = tid + 256;
    const int r0s = i0 >> 2, k0s = (i0 & 3) * 8;
    const int r1s = i1 >> 2, k1s = (i1 & 3) * 8;
    const int bsz0 = (n0 + r0s) < N ? 16 : 0;
    const int bsz1 = (n0 + r1s) < N ? 16 : 0;
    const uint32_t d0 = (uint32_t)(r0s * ASTR + k0s) * 2;
    const uint32_t d1 = (uint32_t)(r1s * ASTR + k1s) * 2;

    const int l7 = lane & 7;
    const uint32_t aRow = mbase + l7 + ((lane >> 3) & 1) * 8;
    const uint32_t aKof = (lane >> 4) * 16;
    const uint32_t bRow = nbase + l7 + (lane >> 4) * 8;
    const uint32_t bKof = ((lane >> 3) & 1) * 16;

    float acc[2][8][4];
    #pragma unroll
    for (int mt = 0; mt < 2; mt++)
        #pragma unroll
        for (int nt = 0; nt < 8; nt++)
            #pragma unroll
            for (int r = 0; r < 4; r++) acc[mt][nt][r] = 0.f;

    const int nk = K / 32;

    auto load_stage = [&](int kt, int s) {
        const int k0 = kt * 32;
        const uint32_t sb = smb + (uint32_t)s * STAGEB;
        cpa16(sb + d0,        A + (size_t)(m0 + r0s) * K + k0 + k0s, 16);
        cpa16(sb + d1,        A + (size_t)(m0 + r1s) * K + k0 + k1s, 16);
        cpa16(sb + BUFB + d0, B + (size_t)(n0 + r0s) * K + k0 + k0s, bsz0);
        cpa16(sb + BUFB + d1, B + (size_t)(n0 + r1s) * K + k0 + k1s, bsz1);
        cpa_commit();
    };

    load_stage(0, 0);

    for (int kt = 0; kt < nk; kt++) {
        if (kt + 1 < nk) load_stage(kt + 1, (kt + 1) & 1);
        if (kt + 1 < nk) cpa_wait<1>(); else cpa_wait<0>();
        __syncthreads();

        const uint32_t sb = smb + (uint32_t)(kt & 1) * STAGEB;
        const uint32_t bA = sb, bB = sb + BUFB;

        #pragma unroll
        for (int kk = 0; kk < 2; kk++) {
            const uint32_t kb = kk * 32;
            uint32_t ah[2][4];
            #pragma unroll
            for (int mt = 0; mt < 2; mt++) {
                const uint32_t ro = (aRow + mt * 16) * (ASTR * 2) + kb + aKof;
                ldm_x4(ah[mt], bA + ro);
            }
            #pragma unroll
            for (int np = 0; np < 4; np++) {
                const uint32_t ro = (bRow + np * 16) * (ASTR * 2) + kb + bKof;
                uint32_t tb[4];
                ldm_x4(tb, bB + ro);
                uint32_t bh0[2] = {tb[0], tb[1]}, bh1[2] = {tb[2], tb[3]};
                #pragma unroll
                for (int mt = 0; mt < 2; mt++) {
                    mma_fp16(acc[mt][np * 2 + 0], ah[mt], bh0);
                    mma_fp16(acc[mt][np * 2 + 1], ah[mt], bh1);
                }
            }
        }
        __syncthreads();
    }

    #pragma unroll
    for (int mt = 0; mt < 2; mt++) {
        #pragma unroll
        for (int nt = 0; nt < 8; nt++) {
            const int n = n0 + nbase + nt * 8 + q * 2;
            if (n < N) {
                #pragma unroll
                for (int half = 0; half < 2; half++) {
                    const int m = m0 + mbase + mt * 16 + g + half * 8;
                    float v0 = acc[mt][nt][half * 2 + 0];
                    float v1 = acc[mt][nt][half * 2 + 1];
                    if (bias0) { v0 += bias0[n]; v1 += bias0[n + 1]; }
                    if (bias1) { v0 += bias1[n]; v1 += bias1[n + 1]; }
                    *(float2*)(C + (size_t)m * ldc + n) = make_float2(v0, v1);
                }
            }
        }
    }
}

// ---------------- fp32 -> fp16, 8 elems/thread ----------------
__global__ void __launch_bounds__(256) cvt_hi8(
    const float* __restrict__ src, __half* __restrict__ hi, int total)
{
    const int i = (blockIdx.x * 256 + threadIdx.x) * 8;
    if (i < total) {
        float4 x0 = *(const float4*)(src + i);
        float4 x1 = *(const float4*)(src + i + 4);
        float xs[8] = {x0.x, x0.y, x0.z, x0.w, x1.x, x1.y, x1.z, x1.w};
        __half h8[8];
        #pragma unroll
        for (int j = 0; j < 8; j++) h8[j] = __float2half_rn(xs[j]);
        *(uint4*)(hi + i) = *(const uint4*)h8;
    }
}

// ------- embed half of A: g_A16[t*64+b][512+k] = fp16(embed[tok][k]) --------
__global__ void __launch_bounds__(256) cvt_embed8(const float* __restrict__ embed,
                                                  const int* __restrict__ captions) {
    const int i = (blockIdx.x * 256 + threadIdx.x) * 8;
    if (i < TT * BB * 512) {
        const int r = i >> 9, k = i & 511;
        const int b = r & 63, t = r >> 6;
        const int tok = captions[b * TT + t];
        const float* sp = embed + (size_t)tok * 512 + k;
        float4 x0 = *(const float4*)sp;
        float4 x1 = *(const float4*)(sp + 4);
        float xs[8] = {x0.x, x0.y, x0.z, x0.w, x1.x, x1.y, x1.z, x1.w};
        __half h8[8];
        #pragma unroll
        for (int j = 0; j < 8; j++) h8[j] = __float2half_rn(xs[j]);
        *(uint4*)(g_A16 + (size_t)r * 1024 + 512 + k) = *(const uint4*)h8;
    }
}

// ---------------- attention logits (parallel, 896 blocks) ----------------
__global__ void __launch_bounds__(256) attn_dot(const float* __restrict__ features,
                                                const float* __restrict__ W_av) {
    const int b   = blockIdx.x;
    const int n0  = blockIdx.y * 14;
    __shared__ float sW[512];
    const int tid = threadIdx.x;
    const int wid = tid >> 5, lane = tid & 31;
    for (int i = tid; i < 512; i += 256) sW[i] = W_av[i];
    __syncthreads();

    const float* fb = features + (size_t)b * NNF * 512;
    for (int n = n0 + wid; n < n0 + 14 && n < NNF; n += 8) {
        const float* fr = fb + (size_t)n * 512;
        float s0 = 0.f, s1 = 0.f, s2 = 0.f, s3 = 0.f;
        #pragma unroll
        for (int i = 0; i < 4; i++) {
            const int o = lane + i * 128;
            s0 = fmaf(fr[o],      sW[o],      s0);
            s1 = fmaf(fr[o + 32], sW[o + 32], s1);
            s2 = fmaf(fr[o + 64], sW[o + 64], s2);
            s3 = fmaf(fr[o + 96], sW[o + 96], s3);
        }
        float s = (s0 + s1) + (s2 + s3);
        #pragma unroll
        for (int o = 16; o; o >>= 1) s += __shfl_down_sync(0xffffffffu, s, o);
        if (!lane) g_attl[b * NNF + n] = s;
    }
}

// -- ctx + fmean, fused softmax weights; ctx written fp16 into all 20 A rows --
__global__ void __launch_bounds__(512) attn_ctx(const float* __restrict__ features) {
    const int b  = blockIdx.x;
    const int v0 = blockIdx.y * 64;
    const int tid = threadIdx.x;
    const int c  = tid & 63;
    const int rg = tid >> 6;          // 0..7, rows rg*25..+24
    __shared__ float sw[NNF];
    __shared__ float sred[16];
    __shared__ float sM, sI;
    __shared__ float pac[8][64];
    __shared__ float pam[8][64];
    const int wid = tid >> 5, lane = tid & 31;

    float m = -3.0e38f;
    if (tid < NNF) { m = g_attl[b * NNF + tid]; sw[tid] = m; }
    #pragma unroll
    for (int o = 16; o; o >>= 1) m = fmaxf(m, __shfl_down_sync(0xffffffffu, m, o));
    if (!lane) sred[wid] = m;
    __syncthreads();
    if (tid == 0) {
        float mm = sred[0];
        #pragma unroll
        for (int i = 1; i < 16; i++) mm = fmaxf(mm, sred[i]);
        sM = mm;
    }
    __syncthreads();
    float e = 0.f;
    if (tid < NNF) { e = __expf(sw[tid] - sM); sw[tid] = e; }
    float s = e;
    #pragma unroll
    for (int o = 16; o; o >>= 1) s += __shfl_down_sync(0xffffffffu, s, o);
    if (!lane) sred[wid] = s;
    __syncthreads();
    if (tid == 0) {
        float ss = 0.f;
        #pragma unroll
        for (int i = 0; i < 16; i++) ss += sred[i];
        sI = 1.f / ss;
    }
    __syncthreads();
    const float inv = sI;

    const float* fp = features + (size_t)b * NNF * 512 + v0 + c;
    float ac = 0.f, am = 0.f;
    const int nb = rg * 25;
    #pragma unroll 5
    for (int j = 0; j < 25; j++) {
        const int n = nb + j;
        if (n < NNF) {
            const float f = fp[(size_t)n * 512];
            ac = fmaf(sw[n], f, ac);
            am += f;
        }
    }
    pac[rg][c] = ac;
    pam[rg][c] = am;
    __syncthreads();
    if (rg == 0) {
        float a = 0.f, mm = 0.f;
        #pragma unroll
        for (int i = 0; i < 8; i++) { a += pac[i][c]; mm += pam[i][c]; }
        g_fmean[b * 512 + v0 + c] = mm * (1.f / (float)NNF);
        const __half ch = __float2half_rn(a * inv);
        #pragma unroll
        for (int t = 0; t < TT; t++)
            g_A16[(size_t)(t * 64 + b) * 1024 + v0 + c] = ch;
    }
}

// ================= persistent HMMA LSTM (phase0 + 20 steps, 1 launch) =========
__device__ __forceinline__ void gbar() {
    __syncthreads();
    if (threadIdx.x == 0) {
        unsigned long long old;
        asm volatile("atom.release.gpu.global.add.u64 %0, [%1], %2;"
                     : "=l"(old) : "l"(&g_bar), "l"(1ULL) : "memory");
        unsigned long long tgt = old - (old & (unsigned long long)(NBLK - 1)) + (unsigned long long)NBLK;
        unsigned long long cur;
        do {
            asm volatile("ld.global.acquire.gpu.u64 %0, [%1];" : "=l"(cur) : "l"(&g_bar));
        } while (cur < tgt);
    }
    __syncthreads();
}

#define STRH 520   // fp16 row stride for sW/sH (1040 B, conflict-free ldmatrix)

__global__ void __launch_bounds__(256, 1) lstm_kernel(
    const float* __restrict__ Winit_h, const float* __restrict__ Winit_c,
    const float* __restrict__ Whh)
{
    extern __shared__ __half smh[];
    __half* sW = smh;                 // [16][STRH]  gate-row weights
    __half* sH = smh + 16 * STRH;     // [64][STRH]  h (fp16)

    const int tid  = threadIdx.x;
    const int w    = tid >> 5;
    const int lane = tid & 31;
    const int l7   = lane & 7;
    const int r    = lane >> 2;       // 0..7
    const int q    = lane & 3;
    const int u0   = blockIdx.x * 4;

    const uint32_t sWb = smem_u32(sW);
    const uint32_t sHb = smem_u32(sH);
    const uint32_t aOff = (uint32_t)((l7 + ((lane >> 3) & 1) * 8) * (STRH * 2) + (lane >> 4) * 16);
    const uint32_t bOff = (uint32_t)((w * 8 + l7) * (STRH * 2) + (lane >> 3) * 16);

    // ---- phase 0: sW rows 0-3 = Winit_h[u0+j], 4-7 = Winit_c[u0+j], 8-15 = 0
    for (int idx = tid; idx < 2048; idx += 256) {
        const int m = idx >> 7, c4 = idx & 127;
        __half2 p0 = __float2half2_rn(0.f), p1 = p0;
        if (m < 8) {
            const float* src = (m < 4) ? (Winit_h + (size_t)(u0 + m) * 512)
                                       : (Winit_c + (size_t)(u0 + m - 4) * 512);
            float4 v = *(const float4*)(src + c4 * 4);
            p0 = __floats2half2_rn(v.x, v.y);
            p1 = __floats2half2_rn(v.z, v.w);
        }
        *(__half2*)(sW + m * STRH + c4 * 4)     = p0;
        *(__half2*)(sW + m * STRH + c4 * 4 + 2) = p1;
    }
    for (int idx = tid; idx < 8192; idx += 256) {
        const int row = idx >> 7, c4 = idx & 127;
        float4 v = *(const float4*)(g_fmean + row * 512 + c4 * 4);
        *(__half2*)(sH + row * STRH + c4 * 4)     = __floats2half2_rn(v.x, v.y);
        *(__half2*)(sH + row * STRH + c4 * 4 + 2) = __floats2half2_rn(v.z, v.w);
    }
    __syncthreads();

    float acc[4] = {0.f, 0.f, 0.f, 0.f};
    #pragma unroll
    for (int kt2 = 0; kt2 < 16; kt2++) {
        uint32_t a0[4], a1[4], tb[4];
        ldm_x4(a0, sWb + aOff + kt2 * 64);
        ldm_x4(a1, sWb + aOff + kt2 * 64 + 32);
        ldm_x4(tb, sHb + bOff + kt2 * 64);
        uint32_t b0v[2] = {tb[0], tb[1]}, b1v[2] = {tb[2], tb[3]};
        mma_fp16(acc, a0, b0v);
        mma_fp16(acc, a1, b1v);
    }
    const int b0i = w * 8 + q * 2;
    float c2[2] = {0.f, 0.f};
    {
        const float cc0 = __shfl_xor_sync(0xffffffffu, acc[0], 16);
        const float cc1 = __shfl_xor_sync(0xffffffffu, acc[1], 16);
        if (lane < 16) {
            c2[0] = cc0; c2[1] = cc1;
            g_hb16[0][b0i * 512 + u0 + r]       = __float2half_rn(acc[0]);
            g_hb16[0][(b0i + 1) * 512 + u0 + r] = __float2half_rn(acc[1]);
        }
    }
    __syncthreads();

    // ---- steady-state weights: sW row m = Whh[(m>>2)*512 + u0 + (m&3)]
    for (int idx = tid; idx < 2048; idx += 256) {
        const int m = idx >> 7, c4 = idx & 127;
        const int grow = (m >> 2) * 512 + u0 + (m & 3);
        float4 v = *(const float4*)(Whh + (size_t)grow * 512 + c4 * 4);
        *(__half2*)(sW + m * STRH + c4 * 4)     = __floats2half2_rn(v.x, v.y);
        *(__half2*)(sW + m * STRH + c4 * 4 + 2) = __floats2half2_rn(v.z, v.w);
    }

    const int m1 = r, m2 = r + 8;
    const int col1 = (m1 >> 2) * 512 + u0 + (m1 & 3);
    const int col2 = (m2 >> 2) * 512 + u0 + (m2 & 3);
    float gp[4];
    {
        const float* gr = g_gpre;
        gp[0] = gr[(size_t)b0i * G4 + col1];
        gp[1] = gr[(size_t)(b0i + 1) * G4 + col1];
        gp[2] = gr[(size_t)b0i * G4 + col2];
        gp[3] = gr[(size_t)(b0i + 1) * G4 + col2];
    }
    gbar();

    for (int t = 0; t < TT; t++) {
        {
            const uint4* src = (const uint4*)g_hb16[t & 1];
            for (int idx = tid; idx < 4096; idx += 256) {
                const int row = idx >> 6, c8 = idx & 63;
                *(uint4*)(sH + row * STRH + c8 * 8) = src[row * 64 + c8];
            }
        }
        __syncthreads();

        acc[0] = gp[0]; acc[1] = gp[1]; acc[2] = gp[2]; acc[3] = gp[3];
        #pragma unroll
        for (int kt2 = 0; kt2 < 16; kt2++) {
            uint32_t a0[4], a1[4], tb[4];
            ldm_x4(a0, sWb + aOff + kt2 * 64);
            ldm_x4(a1, sWb + aOff + kt2 * 64 + 32);
            ldm_x4(tb, sHb + bOff + kt2 * 64);
            uint32_t b0v[2] = {tb[0], tb[1]}, b1v[2] = {tb[2], tb[3]};
            mma_fp16(acc, a0, b0v);
            mma_fp16(acc, a1, b1v);
        }

        const float f0 = __shfl_xor_sync(0xffffffffu, acc[0], 16);
        const float f1 = __shfl_xor_sync(0xffffffffu, acc[1], 16);
        const float o0 = __shfl_xor_sync(0xffffffffu, acc[2], 16);
        const float o1 = __shfl_xor_sync(0xffffffffu, acc[3], 16);
        if (lane < 16) {
            #pragma unroll
            for (int ii = 0; ii < 2; ii++) {
                const float gi = acc[ii];
                const float gg = acc[2 + ii];
                const float gf = ii ? f1 : f0;
                const float go = ii ? o1 : o0;
                const float si = 1.f / (1.f + __expf(-gi));
                const float sf = 1.f / (1.f + __expf(-gf));
                const float so = 1.f / (1.f + __expf(-go));
                c2[ii] = sf * c2[ii] + si * tanhf(gg);
                const float hnew = so * tanhf(c2[ii]);
                const __half hh = __float2half_rn(hnew);
                const int b = b0i + ii;
                g_hb16[(t + 1) & 1][b * 512 + u0 + r] = hh;
                g_hall[(size_t)(t * 64 + b) * 512 + u0 + r] = hh;
            }
        }

        if (t < TT - 1) {
            const float* gr = g_gpre + (size_t)(t + 1) * BB * G4;
            gp[0] = gr[(size_t)b0i * G4 + col1];
            gp[1] = gr[(size_t)(b0i + 1) * G4 + col1];
            gp[2] = gr[(size_t)b0i * G4 + col2];
            gp[3] = gr[(size_t)(b0i + 1) * G4 + col2];
            gbar();
        }
    }
}

// ---------------- fused log_softmax + softmax, 512 threads/row ----------------
__global__ void __launch_bounds__(512) softmax_kernel(float* __restrict__ out) {
    const int r = blockIdx.x;
    const float4* x4 = (const float4*)(g_words + (size_t)r * VOC);
    float4* ols = (float4*)(out + (size_t)r * VOC);
    float4* osm = (float4*)(out + (size_t)TT * BB * VOC + (size_t)r * VOC);

    float m = -3.0e38f, s = 0.f;
    for (int i = threadIdx.x; i < VOC / 4; i += 512) {
        float4 v = x4[i];
        float m4 = fmaxf(fmaxf(v.x, v.y), fmaxf(v.z, v.w));
        float mn = fmaxf(m, m4);
        s = s * __expf(m - mn) + __expf(v.x - mn) + __expf(v.y - mn)
                               + __expf(v.z - mn) + __expf(v.w - mn);
        m = mn;
    }
    #pragma unroll
    for (int o = 16; o; o >>= 1) {
        float m2 = __shfl_down_sync(0xffffffffu, m, o);
        float s2 = __shfl_down_sync(0xffffffffu, s, o);
        float mx = fmaxf(m, m2);
        s = s * __expf(m - mx) + s2 * __expf(m2 - mx);
        m = mx;
    }
    __shared__ float sm[16], ss[16];
    __shared__ float bM, bS;
    const int wid = threadIdx.x >> 5, lane = threadIdx.x & 31;
    if (!lane) { sm[wid] = m; ss[wid] = s; }
    __syncthreads();
    if (threadIdx.x == 0) {
        float M = sm[0], S = ss[0];
        #pragma unroll
        for (int i = 1; i < 16; i++) {
            float mx = fmaxf(M, sm[i]);
            S = S * __expf(M - mx) + ss[i] * __expf(sm[i] - mx);
            M = mx;
        }
        bM = M; bS = S;
    }
    __syncthreads();
    const float M = bM;
    const float Sinv = 1.f / bS;
    const float lg = __logf(bS);
    for (int i = threadIdx.x; i < VOC / 4; i += 512) {
        float4 v = x4[i];
        float4 l4, p4;
        l4.x = v.x - M - lg; p4.x = __expf(v.x - M) * Sinv;
        l4.y = v.y - M - lg; p4.y = __expf(v.y - M) * Sinv;
        l4.z = v.z - M - lg; p4.z = __expf(v.z - M) * Sinv;
        l4.w = v.w - M - lg; p4.w = __expf(v.w - M) * Sinv;
        ols[i] = l4;
        osm[i] = p4;
    }
}

// ---------------- launch ----------------
extern "C" void kernel_launch(void* const* d_in, const int* in_sizes, int n_in,
                              void* d_out, int out_size) {
    (void)in_sizes; (void)n_in; (void)out_size;
    const float* features = (const float*)d_in[0];
    const int*   captions = (const int*)  d_in[1];
    const float* W_init_h = (const float*)d_in[2];
    const float* W_init_c = (const float*)d_in[3];
    const float* W_av     = (const float*)d_in[4];
    // d_in[5] b_av, d_in[6] W_ah, d_in[7] b_ah : dead (softmax shift-invariance)
    const float* embed    = (const float*)d_in[8];
    const float* W_ih     = (const float*)d_in[9];
    const float* W_hh     = (const float*)d_in[10];
    const float* b_ih     = (const float*)d_in[11];
    const float* b_hh     = (const float*)d_in[12];
    const float* W_out    = (const float*)d_in[13];
    const float* b_out    = (const float*)d_in[14];
    float* out = (float*)d_out;

    float *gpre, *words;
    __half *wout16, *wih16, *a16, *hall;
    cudaGetSymbolAddress((void**)&gpre,   g_gpre);
    cudaGetSymbolAddress((void**)&words,  g_words);
    cudaGetSymbolAddress((void**)&wout16, g_Wout16);
    cudaGetSymbolAddress((void**)&wih16,  g_Wih16);
    cudaGetSymbolAddress((void**)&a16,    g_A16);
    cudaGetSymbolAddress((void**)&hall,   g_hall);

    // lazy one-time setup (outside graph capture: first call is the correctness run)
    static bool init_done = false;
    static cudaStream_t sB;
    static cudaEvent_t evFork, evWih, evWout;
    if (!init_done) {
        cudaFuncSetAttribute(lstm_kernel, cudaFuncAttributeMaxDynamicSharedMemorySize,
                             (16 + 64) * STRH * 2);
        cudaFuncSetAttribute(gemm_mma, cudaFuncAttributeMaxDynamicSharedMemorySize, 2 * STAGEB);
        cudaStreamCreateWithFlags(&sB, cudaStreamNonBlocking);
        cudaEventCreateWithFlags(&evFork, cudaEventDisableTiming);
        cudaEventCreateWithFlags(&evWih,  cudaEventDisableTiming);
        cudaEventCreateWithFlags(&evWout, cudaEventDisableTiming);
        init_done = true;
    }
    const int LSTM_SMEM = (16 + 64) * STRH * 2;       // 83200 B
    const int GEMM_SMEM = 2 * STAGEB;                 // 40960 B

    // fork: embed gather + both weight conversions run on sB
    cudaEventRecord(evFork, 0);
    cudaStreamWaitEvent(sB, evFork, 0);
    cvt_embed8<<<(TT * BB * 512 / 8 + 255) / 256, 256, 0, sB>>>(embed, captions);
    cvt_hi8<<<(G4 * 1024 / 8 + 255) / 256, 256, 0, sB>>>(W_ih, wih16, G4 * 1024);
    cudaEventRecord(evWih, sB);
    cvt_hi8<<<(VOC * 512 / 8 + 255) / 256, 256, 0, sB>>>(W_out, wout16, VOC * 512);
    cudaEventRecord(evWout, sB);

    // attention: logits (896 blocks), fused ctx(+fp16 A-rows)+fmean (512 blocks)
    attn_dot<<<dim3(BB, 14), 256>>>(features, W_av);
    attn_ctx<<<dim3(BB, 8), 512>>>(features);

    // gpre = [ctx|emb] @ W_ih^T + b_ih + b_hh   (K=1024), joins embed+W_ih cvt
    cudaStreamWaitEvent(0, evWih, 0);
    gemm_mma<<<dim3(TT * BB / 128, G4 / 128), 256, GEMM_SMEM>>>(
        a16, wih16, gpre, G4, G4, 1024, b_ih, b_hh);

    // persistent HMMA LSTM
    lstm_kernel<<<NBLK, 256, LSTM_SMEM>>>(W_init_h, W_init_c, W_hh);

    // join W_out conversion, then monolithic words GEMM (full-chip, grid 10x79)
    cudaStreamWaitEvent(0, evWout, 0);
    gemm_mma<<<dim3(TT * BB / 128, (VOC + 127) / 128), 256, GEMM_SMEM>>>(
        hall, wout16, words, VOC, VOC, 512, b_out, nullptr);

    // fused log_softmax + softmax (single launch)
    softmax_kernel<<<TT * BB, 512>>>(out);
}